// round 1
// baseline (speedup 1.0000x reference)
#include <cuda_runtime.h>
#include <math.h>

#define T_STEPS 512
#define BATCH   64
#define TB      (T_STEPS*BATCH)   // 32768
#define EMB     400
#define NHID    1150

// ---------------- scratch (device globals: allocation-free) ----------------
__device__ float g_emb[TB*EMB];                         // 52.4 MB
__device__ float g_xg[(size_t)TB*4*NHID];               // 603 MB (max 32768*4600)
__device__ float g_h[2][1152*64];                       // double-buffered hidden state, k-major [k][m]
__device__ unsigned g_count;                            // grid barrier state (zero-init)
__device__ unsigned g_gen;

// ---------------- embedding gather ----------------
__global__ void embed_kernel(const int* __restrict__ tok, const float* __restrict__ ew) {
    int i = blockIdx.x * blockDim.x + threadIdx.x;      // over TB * 100 float4
    if (i < TB * 100) {
        int r = i / 100, c = i - r * 100;
        const float4* src = (const float4*)(ew + (size_t)tok[r] * EMB);
        ((float4*)g_emb)[(size_t)r * 100 + c] = src[c];
    }
}

// ---------------- input projection GEMM: Y[m][n] = sum_k X[m][k]*W[n][k] + bi[n]+bh[n]
#define BM 128
#define BN 64
#define BKK 16

__global__ void __launch_bounds__(256) proj_kernel(
    const float* __restrict__ X, const float* __restrict__ W,
    const float* __restrict__ bi, const float* __restrict__ bh,
    float* __restrict__ Y, int N, int K)
{
    __shared__ float As[BKK][BM + 4];
    __shared__ float Bs[BKK][BN + 4];
    int tid = threadIdx.x;
    int tx = tid & 15, ty = tid >> 4;       // tx: n-dir (16x4), ty: m-dir (16x8)
    int mb = blockIdx.y * BM;
    int nb = blockIdx.x * BN;

    float acc[8][4];
#pragma unroll
    for (int i = 0; i < 8; i++)
#pragma unroll
        for (int j = 0; j < 4; j++) acc[i][j] = 0.f;

    for (int k0 = 0; k0 < K; k0 += BKK) {
        // A tile: 128x16
#pragma unroll
        for (int j = 0; j < 8; j++) {
            int id = j * 256 + tid;
            int m = id >> 4, k = id & 15;
            As[k][m] = (k0 + k < K) ? X[(size_t)(mb + m) * K + k0 + k] : 0.f;
        }
        // B tile: 64x16
#pragma unroll
        for (int j = 0; j < 4; j++) {
            int id = j * 256 + tid;
            int n = id >> 4, k = id & 15;
            float v = 0.f;
            if (k0 + k < K && nb + n < N) v = W[(size_t)(nb + n) * K + k0 + k];
            Bs[k][n] = v;
        }
        __syncthreads();
#pragma unroll
        for (int k = 0; k < BKK; k++) {
            float a[8], b[4];
#pragma unroll
            for (int i = 0; i < 8; i++) a[i] = As[k][ty * 8 + i];
#pragma unroll
            for (int j = 0; j < 4; j++) b[j] = Bs[k][tx * 4 + j];
#pragma unroll
            for (int i = 0; i < 8; i++)
#pragma unroll
                for (int j = 0; j < 4; j++) acc[i][j] += a[i] * b[j];
        }
        __syncthreads();
    }
#pragma unroll
    for (int j = 0; j < 4; j++) {
        int n = nb + tx * 4 + j;
        if (n >= N) continue;
        float bias = bi[n] + bh[n];
#pragma unroll
        for (int i = 0; i < 8; i++) {
            int m = mb + ty * 8 + i;
            Y[(size_t)m * N + n] = acc[i][j] + bias;
        }
    }
}

// ---------------- zero hidden state buffer 0 ----------------
__global__ void zero_h_kernel(int n) {
    int i = blockIdx.x * blockDim.x + threadIdx.x;
    if (i < n) g_h[0][i] = 0.f;
}

// ---------------- grid barrier (all blocks co-resident) ----------------
__device__ __forceinline__ void grid_barrier(int nb) {
    __threadfence();
    __syncthreads();
    if (threadIdx.x == 0) {
        volatile unsigned* genp = &g_gen;
        unsigned g = *genp;
        unsigned old = atomicAdd(&g_count, 1u);
        if (old == (unsigned)(nb - 1)) {
            g_count = 0;
            __threadfence();
            atomicAdd(&g_gen, 1u);
        } else {
            while (*genp == g) { }
        }
    }
    __syncthreads();
    __threadfence();
}

__device__ __forceinline__ float sigmoidf_(float x) { return 1.f / (1.f + expf(-x)); }

// ---------------- persistent LSTM scan ----------------
// H: real hidden size, HP: padded (mult of 64), U: hidden units per block, NT: n-tile per thread
// Block owns gate rows n = q*U + ui (q=0..3 gates i,f,g,o), units [u0, u0+U).
template<int H, int HP, int U, int NT>
__global__ void __launch_bounds__(128, 1) scan_kernel(
    const float* __restrict__ xg, const float* __restrict__ whh,
    float* __restrict__ out, int nb)
{
    constexpr int N  = 4 * U;       // gate rows per block
    constexpr int NS = N + 1;       // padded gate_s stride
    constexpr int KC = 64;
    constexpr int NCH = HP / KC;
    constexpr int G  = 4 * H;

    extern __shared__ float sm[];
    float* Ws     = sm;                   // [HP][N]
    float* hs     = Ws + HP * N;          // [KC][64]
    float* gate_s = hs + KC * 64;         // [64][NS]
    float* cs     = gate_s + 64 * NS;     // [64][U+1]

    int tid = threadIdx.x;
    int u0 = blockIdx.x * U;
    int nx = tid & 7, my = tid >> 3;      // nx: 0..7 (n-dir), my: 0..15 (m-dir)

    // Load W_hh chunk into SMEM, [k][n] layout, zero padding
    for (int idx = tid; idx < N * HP; idx += 128) {
        int n = idx / HP, k = idx - n * HP;
        int q = n / U, ui = n - q * U;
        int unit = u0 + ui;
        float v = 0.f;
        if (k < H && unit < H) v = whh[((size_t)(q * H + unit)) * H + k];
        Ws[k * N + n] = v;
    }
    for (int idx = tid; idx < 64 * (U + 1); idx += 128) cs[idx] = 0.f;
    __syncthreads();

    for (int t = 0; t < T_STEPS; t++) {
        int r = t & 1, w = r ^ 1;
        const float* hb = g_h[r];
        float* hw = g_h[w];

        float acc[4][NT];
#pragma unroll
        for (int i = 0; i < 4; i++)
#pragma unroll
            for (int j = 0; j < NT; j++) acc[i][j] = 0.f;

        // prefetch chunk 0 of h (L2 loads: bypass L1, other SMs rewrote it)
        float4 pf[8];
        {
            const float4* src = (const float4*)hb;
#pragma unroll
            for (int j = 0; j < 8; j++) pf[j] = __ldcg(&src[j * 128 + tid]);
        }

        for (int c = 0; c < NCH; c++) {
            __syncthreads();
#pragma unroll
            for (int j = 0; j < 8; j++) ((float4*)hs)[j * 128 + tid] = pf[j];
            __syncthreads();
            if (c + 1 < NCH) {
                const float4* src = (const float4*)(hb + (c + 1) * KC * 64);
#pragma unroll
                for (int j = 0; j < 8; j++) pf[j] = __ldcg(&src[j * 128 + tid]);
            }
#pragma unroll 8
            for (int k = 0; k < KC; k++) {
                float4 hv = *(const float4*)&hs[k * 64 + my * 4];
                float wv[NT];
                if constexpr (NT == 4) {
                    float4 w4 = *(const float4*)&Ws[(c * KC + k) * N + nx * 4];
                    wv[0] = w4.x; wv[1] = w4.y; wv[2] = w4.z; wv[3] = w4.w;
                } else {
                    float2 w2 = *(const float2*)&Ws[(c * KC + k) * N + nx * 2];
                    wv[0] = w2.x; wv[1] = w2.y;
                }
                float hvv[4] = {hv.x, hv.y, hv.z, hv.w};
#pragma unroll
                for (int i = 0; i < 4; i++)
#pragma unroll
                    for (int j = 0; j < NT; j++) acc[i][j] += hvv[i] * wv[j];
            }
        }

        // exchange gates via SMEM
#pragma unroll
        for (int i = 0; i < 4; i++) {
            int m = my * 4 + i;
#pragma unroll
            for (int j = 0; j < NT; j++) gate_s[m * NS + nx * NT + j] = acc[i][j];
        }
        __syncthreads();

        // epilogue: each thread handles U/2 (m, unit) pairs
        const float* xgt = xg + (size_t)t * 64 * G;
#pragma unroll
        for (int j = 0; j < U / 2; j++) {
            int p = j * 128 + tid;
            int uu = p % U;
            int m  = p / U;
            int unit = u0 + uu;
            float hval = 0.f;
            if (unit < H) {
                const float* xr = xgt + (size_t)m * G + unit;
                float iraw = gate_s[m * NS + 0 * U + uu] + xr[0];
                float fraw = gate_s[m * NS + 1 * U + uu] + xr[H];
                float graw = gate_s[m * NS + 2 * U + uu] + xr[2 * H];
                float oraw = gate_s[m * NS + 3 * U + uu] + xr[3 * H];
                float cold = cs[m * (U + 1) + uu];
                float cnew = sigmoidf_(fraw) * cold + sigmoidf_(iraw) * tanhf(graw);
                cs[m * (U + 1) + uu] = cnew;
                hval = sigmoidf_(oraw) * tanhf(cnew);
                out[((size_t)t * 64 + m) * H + unit] = hval;
            }
            hw[(u0 + uu) * 64 + m] = hval;
        }
        grid_barrier(nb);
    }
}

// ---------------- launch ----------------
extern "C" void kernel_launch(void* const* d_in, const int* in_sizes, int n_in,
                              void* d_out, int out_size)
{
    (void)in_sizes; (void)n_in; (void)out_size;
    const int*   tok = (const int*)d_in[0];
    const float* ew  = (const float*)d_in[1];
    const float* wih[3] = {(const float*)d_in[2], (const float*)d_in[6],  (const float*)d_in[10]};
    const float* whh[3] = {(const float*)d_in[3], (const float*)d_in[7],  (const float*)d_in[11]};
    const float* bih[3] = {(const float*)d_in[4], (const float*)d_in[8],  (const float*)d_in[12]};
    const float* bhh[3] = {(const float*)d_in[5], (const float*)d_in[9],  (const float*)d_in[13]};

    float* out  = (float*)d_out;
    float* out0 = out;
    float* out1 = out0 + (size_t)TB * NHID;
    float* out2 = out1 + (size_t)TB * NHID;

    void* emb_p = nullptr; cudaGetSymbolAddress(&emb_p, g_emb);
    void* xg_p  = nullptr; cudaGetSymbolAddress(&xg_p,  g_xg);
    const float* embf = (const float*)emb_p;
    float* xgf = (float*)xg_p;

    // dynamic SMEM sizes
    const int SMEM0 = (1152 * 32 + 64 * 64 + 64 * 33 + 64 * 9) * 4;   // 174,592 B
    const int SMEM2 = (448 * 16 + 64 * 64 + 64 * 17 + 64 * 5) * 4;    //  50,688 B
    cudaFuncSetAttribute(scan_kernel<1150, 1152, 8, 4>,
                         cudaFuncAttributeMaxDynamicSharedMemorySize, SMEM0);
    cudaFuncSetAttribute(scan_kernel<400, 448, 4, 2>,
                         cudaFuncAttributeMaxDynamicSharedMemorySize, SMEM2);

    // embedding
    embed_kernel<<<(TB * 100 + 255) / 256, 256>>>(tok, ew);

    dim3 pgBig((4600 + BN - 1) / BN, TB / BM);   // 72 x 256
    dim3 pgSm((1600 + BN - 1) / BN, TB / BM);    // 25 x 256
    const int ZN = 1152 * 64;

    // ---- layer 0: 400 -> 1150 ----
    proj_kernel<<<pgBig, 256>>>(embf, wih[0], bih[0], bhh[0], xgf, 4 * NHID, EMB);
    zero_h_kernel<<<(ZN + 255) / 256, 256>>>(ZN);
    scan_kernel<1150, 1152, 8, 4><<<144, 128, SMEM0>>>(xgf, whh[0], out0, 144);

    // ---- layer 1: 1150 -> 1150 ----
    proj_kernel<<<pgBig, 256>>>(out0, wih[1], bih[1], bhh[1], xgf, 4 * NHID, NHID);
    zero_h_kernel<<<(ZN + 255) / 256, 256>>>(ZN);
    scan_kernel<1150, 1152, 8, 4><<<144, 128, SMEM0>>>(xgf, whh[1], out1, 144);

    // ---- layer 2: 1150 -> 400 ----
    proj_kernel<<<pgSm, 256>>>(out1, wih[2], bih[2], bhh[2], xgf, 4 * 400, NHID);
    zero_h_kernel<<<(ZN + 255) / 256, 256>>>(ZN);
    scan_kernel<400, 448, 4, 2><<<112, 128, SMEM2>>>(xgf, whh[2], out2, 112);
}